// round 13
// baseline (speedup 1.0000x reference)
#include <cuda_runtime.h>
#include <cuda_fp16.h>
#include <cuda_bf16.h>
#include <cstdint>
#include <math.h>

#define N_NODES 200000
#define N_EDGES 800000
#define N_GRAPHS 4096
#define IN_FEAT 64
#define CAT_W 1024
#define N_TILES 1569            // max node tiles of 128 incl. bucket padding
#define PERM_SZ (N_TILES * 128)

// ---------------- device scratch (statically allocated; no cudaMalloc) ------
__device__ int   g_deg[N_NODES];
__device__ int   g_cnt[8];
__device__ int   g_cur[8];
__device__ int   g_pad_off[8];
__device__ int   g_perm[PERM_SZ];
__device__ int   g_eoff[N_NODES + 1];
__device__ int   g_ecur[N_NODES];
__device__ int   g_esrc[N_EDGES];
__device__ int   g_goff[N_GRAPHS + 1];
__device__ float g_cat[(size_t)N_NODES * CAT_W];    // h0@0, h1@128, h2@256, h3@512
__device__ float g_pool[(size_t)N_GRAPHS * 256];

// ---------------- small prep kernels ---------------------------------------
__global__ void deg_kernel(const int* __restrict__ dst) {
    int e = blockIdx.x * blockDim.x + threadIdx.x;
    if (e < N_EDGES) atomicAdd(&g_deg[dst[e]], 1);
}

__global__ void count_kernel() {
    __shared__ int h[6];
    if (threadIdx.x < 6) h[threadIdx.x] = 0;
    __syncthreads();
    int i = blockIdx.x * blockDim.x + threadIdx.x;
    if (i < N_NODES) atomicAdd(&h[min(g_deg[i], 5)], 1);
    __syncthreads();
    if (threadIdx.x < 6 && h[threadIdx.x]) atomicAdd(&g_cnt[threadIdx.x], h[threadIdx.x]);
}

__global__ void scan_kernel() {
    if (threadIdx.x == 0 && blockIdx.x == 0) {
        int off = 0;
        for (int b = 0; b < 6; b++) {
            g_pad_off[b] = off;
            off += ((g_cnt[b] + 127) >> 7) << 7;   // pad each bucket to 128
        }
        g_pad_off[6] = off;
    }
}

__global__ void scatter_kernel() {
    __shared__ int h[6], base[6];
    if (threadIdx.x < 6) h[threadIdx.x] = 0;
    __syncthreads();
    int i = blockIdx.x * blockDim.x + threadIdx.x;
    int b = -1, r = 0;
    if (i < N_NODES) {
        b = min(g_deg[i], 5);
        r = atomicAdd(&h[b], 1);
    }
    __syncthreads();
    if (threadIdx.x < 6 && h[threadIdx.x]) base[threadIdx.x] = atomicAdd(&g_cur[threadIdx.x], h[threadIdx.x]);
    __syncthreads();
    if (b >= 0) g_perm[g_pad_off[b] + base[b] + r] = i;
}

__global__ void scan_deg_kernel() {
    __shared__ int part[1024];
    const int tid = threadIdx.x;
    const int chunk = (N_NODES + 1023) / 1024;
    int s0 = tid * chunk;
    int s1 = min(s0 + chunk, N_NODES);
    int s = 0;
    for (int i = s0; i < s1; i++) s += g_deg[i];
    part[tid] = s;
    __syncthreads();
    for (int off = 1; off < 1024; off <<= 1) {
        int v = (tid >= off) ? part[tid - off] : 0;
        __syncthreads();
        part[tid] += v;
        __syncthreads();
    }
    int base = (tid == 0) ? 0 : part[tid - 1];
    for (int i = s0; i < s1; i++) {
        g_eoff[i] = base;
        base += g_deg[i];
    }
    if (tid == 1023) g_eoff[N_NODES] = N_EDGES;
}

__global__ void csr_scatter_kernel(const int* __restrict__ src, const int* __restrict__ dst) {
    int e = blockIdx.x * blockDim.x + threadIdx.x;
    if (e >= N_EDGES) return;
    int d = dst[e];
    int pos = atomicAdd(&g_ecur[d], 1);
    g_esrc[g_eoff[d] + pos] = src[e];
}

__global__ void goff_kernel(const int* __restrict__ batch) {
    int i = blockIdx.x * blockDim.x + threadIdx.x;
    if (i >= N_NODES) return;
    int bc = batch[i];
    if (i == 0) {
        for (int g = 0; g <= bc; g++) g_goff[g] = 0;
    } else {
        int bp = batch[i - 1];
        for (int g = bp + 1; g <= bc; g++) g_goff[g] = i;
    }
    if (i == N_NODES - 1) {
        for (int g = bc + 1; g <= N_GRAPHS; g++) g_goff[g] = N_NODES;
    }
}

// ---------------- fp16 3-term emulation helpers ------------------------------
// pack (v0,v1) as fp16x2 hi and fp16x2 lo (residual); drops only lo*lo (~2^-22)
__device__ __forceinline__ void split_pack(float v0, float v1, uint32_t& hi, uint32_t& lo) {
    __half h0 = __float2half_rn(v0);
    __half h1 = __float2half_rn(v1);
    __half l0 = __float2half_rn(v0 - __half2float(h0));
    __half l1 = __float2half_rn(v1 - __half2float(h1));
    __half2 H = __halves2half2(h0, h1);
    __half2 L = __halves2half2(l0, l1);
    hi = *(uint32_t*)&H;
    lo = *(uint32_t*)&L;
}

__device__ __forceinline__ void mma_f16(float* c, const uint32_t* a, const uint32_t* b) {
    asm volatile(
        "mma.sync.aligned.m16n8k16.row.col.f32.f16.f16.f32 "
        "{%0,%1,%2,%3}, {%4,%5,%6,%7}, {%8,%9}, {%0,%1,%2,%3};"
        : "+f"(c[0]), "+f"(c[1]), "+f"(c[2]), "+f"(c[3])
        : "r"(a[0]), "r"(a[1]), "r"(a[2]), "r"(a[3]), "r"(b[0]), "r"(b[1]));
}

// ---------------- bucketed grouped GEMM (3xFP16 + fused aggregation) --------
// A = [msg | x] where msg is gathered ON THE FLY from CSR (no g_msg buffer):
//   msg[node][k] = sum_e in[esrc[e]][k].  K = 2*CIN; rows via g_perm (one bucket/tile).
// B = [Wl[d] ; Wr[d]]   out = A@B + bl[d]
// Block: 128 rows x 128 cols, 256 thr (8 warps; warp tile 64x32).
// fp32 accuracy via hi/lo fp16 split: A_hi*B_lo + A_lo*B_hi + A_hi*B_hh.
template <int CIN, int COUT>
__launch_bounds__(256, 2)
__global__ void gemm_kernel(const float* __restrict__ in, int in_stride,
                            float* __restrict__ out,
                            const float* __restrict__ Wl,
                            const float* __restrict__ bl,
                            const float* __restrict__ Wr) {
    constexpr int K = 2 * CIN;
    constexpr int NCH = K / 16;
    __shared__ uint32_t AsH[8][136];   // [k2][row], 136 -> bank rotate 8 per k2
    __shared__ uint32_t AsL[8][136];
    __shared__ uint32_t BsH[8][136];   // [k2][col]
    __shared__ uint32_t BsL[8][136];

    const int row0 = blockIdx.x * 128;
    if (row0 >= g_pad_off[6]) return;

    int d = 0;
    #pragma unroll
    for (int b = 1; b < 6; b++)
        if (row0 >= g_pad_off[b]) d = b;

    const int ocol0 = blockIdx.y * 128;
    const int t = threadIdx.x;
    const int lane = t & 31;
    const int warp = t >> 5;
    const int wm = (warp >> 2) * 64;      // warp row base
    const int wn = (warp & 3) * 32;       // warp col base
    const int lq = lane & 3;              // quad index (k2 offset)
    const int lg = lane >> 2;             // group index

    // A loader: 2 threads per row, 8 consecutive k (= 4 k-pairs) each
    const int arow = t >> 1, akb = (t & 1) * 8, ak2 = (t & 1) * 4;
    const int anode = g_perm[row0 + arow];
    const int e0 = (anode >= 0) ? g_eoff[anode] : 0;
    const int e1 = (anode >= 0) ? g_eoff[anode + 1] : 0;
    // B loader: t>>5 = k2 (0..7), (t&31)*4 = col block of 4
    const int bk2 = t >> 5, bcb = (t & 31) * 4;

    const float* WlB = Wl + (size_t)d * CIN * COUT;
    const float* WrB = Wr + (size_t)d * CIN * COUT;

    float acc[4][4][4];
    #pragma unroll
    for (int mt = 0; mt < 4; mt++)
        #pragma unroll
        for (int nt = 0; nt < 4; nt++)
            #pragma unroll
            for (int i = 0; i < 4; i++) acc[mt][nt][i] = 0.f;

    float ar[8], br0[4], br1[4];

    auto load_regs = [&](int k0) {
        int ka = k0 + akb;
        if (anode >= 0) {
            if (ka < CIN) {
                // fused neighbor-sum gather: msg slice [ka, ka+8)
                float4 a0 = make_float4(0.f, 0.f, 0.f, 0.f);
                float4 a1 = a0;
                for (int e = e0; e < e1; e++) {
                    int s = g_esrc[e];
                    const float* p = in + (size_t)s * in_stride + ka;
                    float4 v0 = *(const float4*)p;
                    float4 v1 = *(const float4*)(p + 4);
                    a0.x += v0.x; a0.y += v0.y; a0.z += v0.z; a0.w += v0.w;
                    a1.x += v1.x; a1.y += v1.y; a1.z += v1.z; a1.w += v1.w;
                }
                *(float4*)&ar[0] = a0;
                *(float4*)&ar[4] = a1;
            } else {
                const float* s = in + (size_t)anode * in_stride + (ka - CIN);
                *(float4*)&ar[0] = *(const float4*)s;
                *(float4*)&ar[4] = *(const float4*)(s + 4);
            }
        } else {
            #pragma unroll
            for (int i = 0; i < 8; i++) ar[i] = 0.f;
        }
        // B: rows k = 2*bk2 and 2*bk2+1 of W (k-major), cols bcb..bcb+3
        int kb0 = k0 + 2 * bk2;
        const float* w0 = (kb0 < CIN) ? (WlB + (size_t)kb0 * COUT + ocol0 + bcb)
                                      : (WrB + (size_t)(kb0 - CIN) * COUT + ocol0 + bcb);
        int kb1 = kb0 + 1;
        const float* w1 = (kb1 < CIN) ? (WlB + (size_t)kb1 * COUT + ocol0 + bcb)
                                      : (WrB + (size_t)(kb1 - CIN) * COUT + ocol0 + bcb);
        *(float4*)&br0[0] = *(const float4*)w0;
        *(float4*)&br1[0] = *(const float4*)w1;
    };

    auto store_smem = [&]() {
        #pragma unroll
        for (int j = 0; j < 4; j++) {
            uint32_t h, l;
            split_pack(ar[2 * j], ar[2 * j + 1], h, l);
            AsH[ak2 + j][arow] = h;
            AsL[ak2 + j][arow] = l;
        }
        uint4 h4, l4;
        split_pack(br0[0], br1[0], h4.x, l4.x);
        split_pack(br0[1], br1[1], h4.y, l4.y);
        split_pack(br0[2], br1[2], h4.z, l4.z);
        split_pack(br0[3], br1[3], h4.w, l4.w);
        *(uint4*)&BsH[bk2][bcb] = h4;
        *(uint4*)&BsL[bk2][bcb] = l4;
    };

    load_regs(0);

    for (int ch = 0; ch < NCH; ch++) {
        __syncthreads();          // previous chunk's compute done
        store_smem();
        __syncthreads();
        if (ch + 1 < NCH) load_regs((ch + 1) * 16);   // gather overlaps compute

        // one m16n8k16 step covers the whole 16-k chunk
        uint32_t bh[4][2], blo[4][2];
        #pragma unroll
        for (int nt = 0; nt < 4; nt++) {
            int cb = wn + nt * 8 + lg;
            bh[nt][0]  = BsH[lq][cb];
            bh[nt][1]  = BsH[lq + 4][cb];
            blo[nt][0] = BsL[lq][cb];
            blo[nt][1] = BsL[lq + 4][cb];
        }
        #pragma unroll
        for (int mt = 0; mt < 4; mt++) {
            int rb = wm + mt * 16 + lg;
            uint32_t ah[4], al[4];
            ah[0] = AsH[lq][rb];     ah[1] = AsH[lq][rb + 8];
            ah[2] = AsH[lq + 4][rb]; ah[3] = AsH[lq + 4][rb + 8];
            al[0] = AsL[lq][rb];     al[1] = AsL[lq][rb + 8];
            al[2] = AsL[lq + 4][rb]; al[3] = AsL[lq + 4][rb + 8];
            #pragma unroll
            for (int nt = 0; nt < 4; nt++) {
                mma_f16(acc[mt][nt], ah, blo[nt]);   // hi * lo
                mma_f16(acc[mt][nt], al, bh[nt]);    // lo * hi
                mma_f16(acc[mt][nt], ah, bh[nt]);    // hi * hi
            }
        }
    }

    // ---- epilogue: +bias, scatter rows back to node indices
    #pragma unroll
    for (int mt = 0; mt < 4; mt++) {
        int r0 = row0 + wm + mt * 16 + lg;
        int n0 = g_perm[r0];
        int n1 = g_perm[r0 + 8];
        #pragma unroll
        for (int nt = 0; nt < 4; nt++) {
            int col = wn + nt * 8 + 2 * lq;
            float b0 = bl[(size_t)d * COUT + ocol0 + col];
            float b1 = bl[(size_t)d * COUT + ocol0 + col + 1];
            if (n0 >= 0) {
                float2 v = make_float2(acc[mt][nt][0] + b0, acc[mt][nt][1] + b1);
                *(float2*)(out + (size_t)n0 * CAT_W + ocol0 + col) = v;
            }
            if (n1 >= 0) {
                float2 v = make_float2(acc[mt][nt][2] + b0, acc[mt][nt][3] + b1);
                *(float2*)(out + (size_t)n1 * CAT_W + ocol0 + col) = v;
            }
        }
    }
}

// ---------------- segmented global add pool of h3 over batch -----------------
__global__ void pool_seg_kernel() {
    int idx = blockIdx.x * blockDim.x + threadIdx.x;
    if (idx >= N_GRAPHS * 64) return;
    int g = idx >> 6;
    int c = (idx & 63) * 4;
    int i0 = g_goff[g], i1 = g_goff[g + 1];
    float4 acc = make_float4(0.f, 0.f, 0.f, 0.f);
    for (int i = i0; i < i1; i++) {
        float4 v = *(const float4*)(g_cat + (size_t)i * CAT_W + 512 + c);
        acc.x += v.x; acc.y += v.y; acc.z += v.z; acc.w += v.w;
    }
    *(float4*)(g_pool + (size_t)g * 256 + c) = acc;
}

// ---------------- final linear (1024 -> 2) + softmax -------------------------
__launch_bounds__(256)
__global__ void final_kernel(const float* __restrict__ Wf, const float* __restrict__ bf,
                             const int* __restrict__ batch, float* __restrict__ out) {
    __shared__ float wf_s[CAT_W * 2];
    for (int i = threadIdx.x; i < CAT_W * 2; i += 256) wf_s[i] = Wf[i];
    __syncthreads();

    int warp = threadIdx.x >> 5, lane = threadIdx.x & 31;
    int node = blockIdx.x * 8 + warp;
    if (node >= N_NODES) return;

    const float* row = g_cat + (size_t)node * CAT_W;
    const float* prow = g_pool + (size_t)batch[node] * 256;

    float s0 = 0.f, s1 = 0.f;
    #pragma unroll
    for (int j = 0; j < 24; j++) {
        int c = j * 32 + lane;
        float v = row[c];
        s0 += v * wf_s[2 * c];
        s1 += v * wf_s[2 * c + 1];
    }
    #pragma unroll
    for (int j = 0; j < 8; j++) {
        int c = j * 32 + lane;
        float v = prow[c];
        int cc = 768 + c;
        s0 += v * wf_s[2 * cc];
        s1 += v * wf_s[2 * cc + 1];
    }
    #pragma unroll
    for (int off = 16; off; off >>= 1) {
        s0 += __shfl_down_sync(0xFFFFFFFFu, s0, off);
        s1 += __shfl_down_sync(0xFFFFFFFFu, s1, off);
    }
    if (lane == 0) {
        float l0 = s0 + bf[0], l1 = s1 + bf[1];
        float m = fmaxf(l0, l1);
        float e0 = expf(l0 - m), e1 = expf(l1 - m);
        float inv = 1.f / (e0 + e1);
        out[(size_t)node * 2 + 0] = e0 * inv;
        out[(size_t)node * 2 + 1] = e1 * inv;
    }
}

// ---------------- host orchestration ----------------------------------------
extern "C" void kernel_launch(void* const* d_in, const int* in_sizes, int n_in,
                              void* d_out, int out_size) {
    const float* x     = (const float*)d_in[0];
    const int*   ei    = (const int*)d_in[1];
    const int*   batch = (const int*)d_in[2];
    const float* Wl[4] = {(const float*)d_in[3], (const float*)d_in[6], (const float*)d_in[9],  (const float*)d_in[12]};
    const float* bl[4] = {(const float*)d_in[4], (const float*)d_in[7], (const float*)d_in[10], (const float*)d_in[13]};
    const float* Wr[4] = {(const float*)d_in[5], (const float*)d_in[8], (const float*)d_in[11], (const float*)d_in[14]};
    const float* Wf = (const float*)d_in[15];
    const float* bf = (const float*)d_in[16];
    float* out = (float*)d_out;

    const int* src = ei;
    const int* dst = ei + N_EDGES;

    void *p_deg, *p_cnt, *p_cur, *p_perm, *p_ecur, *p_cat;
    cudaGetSymbolAddress(&p_deg, g_deg);
    cudaGetSymbolAddress(&p_cnt, g_cnt);
    cudaGetSymbolAddress(&p_cur, g_cur);
    cudaGetSymbolAddress(&p_perm, g_perm);
    cudaGetSymbolAddress(&p_ecur, g_ecur);
    cudaGetSymbolAddress(&p_cat, g_cat);

    float* cat = (float*)p_cat;

    // ---- degree + bucketed permutation + CSR + graph offsets
    cudaMemsetAsync(p_deg, 0, N_NODES * sizeof(int));
    cudaMemsetAsync(p_cnt, 0, 8 * sizeof(int));
    cudaMemsetAsync(p_cur, 0, 8 * sizeof(int));
    cudaMemsetAsync(p_ecur, 0, N_NODES * sizeof(int));
    cudaMemsetAsync(p_perm, 0xFF, PERM_SZ * sizeof(int));   // -1 everywhere

    deg_kernel<<<(N_EDGES + 255) / 256, 256>>>(dst);
    count_kernel<<<(N_NODES + 255) / 256, 256>>>();
    scan_kernel<<<1, 32>>>();
    scatter_kernel<<<(N_NODES + 255) / 256, 256>>>();
    scan_deg_kernel<<<1, 1024>>>();
    csr_scatter_kernel<<<(N_EDGES + 255) / 256, 256>>>(src, dst);
    goff_kernel<<<(N_NODES + 255) / 256, 256>>>(batch);

    // ---- layer 0: c_in=64 (input x) -> c_out=128 at cat col 0  (agg fused)
    gemm_kernel<64, 128><<<dim3(N_TILES, 1), 256>>>(x, IN_FEAT, cat + 0, Wl[0], bl[0], Wr[0]);

    // ---- layer 1: c_in=128 (cat col 0) -> c_out=128 at cat col 128
    gemm_kernel<128, 128><<<dim3(N_TILES, 1), 256>>>(cat + 0, CAT_W, cat + 128, Wl[1], bl[1], Wr[1]);

    // ---- layer 2: c_in=128 (cat col 128) -> c_out=256 at cat col 256
    gemm_kernel<128, 256><<<dim3(N_TILES, 2), 256>>>(cat + 128, CAT_W, cat + 256, Wl[2], bl[2], Wr[2]);

    // ---- layer 3: c_in=256 (cat col 256) -> c_out=256 at cat col 512
    gemm_kernel<256, 256><<<dim3(N_TILES, 2), 256>>>(cat + 256, CAT_W, cat + 512, Wl[3], bl[3], Wr[3]);

    // ---- segmented pool of h3, then final linear + softmax
    pool_seg_kernel<<<(N_GRAPHS * 64 + 255) / 256, 256>>>();
    final_kernel<<<N_NODES / 8, 256>>>(Wf, bf, batch, out);
}

// round 14
// speedup vs baseline: 1.3188x; 1.3188x over previous
#include <cuda_runtime.h>
#include <cuda_fp16.h>
#include <cuda_bf16.h>
#include <cstdint>
#include <math.h>

#define N_NODES 200000
#define N_EDGES 800000
#define N_GRAPHS 4096
#define IN_FEAT 64
#define N_TILES 1569            // max node tiles of 128 incl. bucket padding
#define PERM_SZ (N_TILES * 128)

// ---------------- device scratch (statically allocated; no cudaMalloc) ------
__device__ int   g_deg[N_NODES];
__device__ int   g_cnt[8];
__device__ int   g_cur[8];
__device__ int   g_pad_off[8];
__device__ int   g_perm[PERM_SZ];
__device__ int   g_eoff[N_NODES + 1];
__device__ int   g_ecur[N_NODES];
__device__ int   g_esrc[N_EDGES];
__device__ int   g_goff[N_GRAPHS + 1];
__device__ float g_msg[(size_t)N_NODES * 256];
__device__ float g_h0[(size_t)N_NODES * 128];
__device__ float g_h1[(size_t)N_NODES * 128];
__device__ float g_h2[(size_t)N_NODES * 256];
__device__ float g_h3[(size_t)N_NODES * 256];
__device__ float g_logit[(size_t)N_NODES * 2];
__device__ float g_pool[(size_t)N_GRAPHS * 256];
__device__ float g_pgl[(size_t)N_GRAPHS * 2];

// ---------------- small prep kernels ---------------------------------------
__global__ void deg_kernel(const int* __restrict__ dst) {
    int e = blockIdx.x * blockDim.x + threadIdx.x;
    if (e < N_EDGES) atomicAdd(&g_deg[dst[e]], 1);
}

__global__ void count_kernel() {
    __shared__ int h[6];
    if (threadIdx.x < 6) h[threadIdx.x] = 0;
    __syncthreads();
    int i = blockIdx.x * blockDim.x + threadIdx.x;
    if (i < N_NODES) atomicAdd(&h[min(g_deg[i], 5)], 1);
    __syncthreads();
    if (threadIdx.x < 6 && h[threadIdx.x]) atomicAdd(&g_cnt[threadIdx.x], h[threadIdx.x]);
}

__global__ void scan_kernel() {
    if (threadIdx.x == 0 && blockIdx.x == 0) {
        int off = 0;
        for (int b = 0; b < 6; b++) {
            g_pad_off[b] = off;
            off += ((g_cnt[b] + 127) >> 7) << 7;   // pad each bucket to 128
        }
        g_pad_off[6] = off;
    }
}

__global__ void scatter_kernel() {
    __shared__ int h[6], base[6];
    if (threadIdx.x < 6) h[threadIdx.x] = 0;
    __syncthreads();
    int i = blockIdx.x * blockDim.x + threadIdx.x;
    int b = -1, r = 0;
    if (i < N_NODES) {
        b = min(g_deg[i], 5);
        r = atomicAdd(&h[b], 1);
    }
    __syncthreads();
    if (threadIdx.x < 6 && h[threadIdx.x]) base[threadIdx.x] = atomicAdd(&g_cur[threadIdx.x], h[threadIdx.x]);
    __syncthreads();
    if (b >= 0) g_perm[g_pad_off[b] + base[b] + r] = i;
}

__global__ void scan_deg_kernel() {
    __shared__ int part[1024];
    const int tid = threadIdx.x;
    const int chunk = (N_NODES + 1023) / 1024;
    int s0 = tid * chunk;
    int s1 = min(s0 + chunk, N_NODES);
    int s = 0;
    for (int i = s0; i < s1; i++) s += g_deg[i];
    part[tid] = s;
    __syncthreads();
    for (int off = 1; off < 1024; off <<= 1) {
        int v = (tid >= off) ? part[tid - off] : 0;
        __syncthreads();
        part[tid] += v;
        __syncthreads();
    }
    int base = (tid == 0) ? 0 : part[tid - 1];
    for (int i = s0; i < s1; i++) {
        g_eoff[i] = base;
        base += g_deg[i];
    }
    if (tid == 1023) g_eoff[N_NODES] = N_EDGES;
}

__global__ void csr_scatter_kernel(const int* __restrict__ src, const int* __restrict__ dst) {
    int e = blockIdx.x * blockDim.x + threadIdx.x;
    if (e >= N_EDGES) return;
    int d = dst[e];
    int pos = atomicAdd(&g_ecur[d], 1);
    g_esrc[g_eoff[d] + pos] = src[e];
}

__global__ void goff_kernel(const int* __restrict__ batch) {
    int i = blockIdx.x * blockDim.x + threadIdx.x;
    if (i >= N_NODES) return;
    int bc = batch[i];
    if (i == 0) {
        for (int g = 0; g <= bc; g++) g_goff[g] = 0;
    } else {
        int bp = batch[i - 1];
        for (int g = bp + 1; g <= bc; g++) g_goff[g] = i;
    }
    if (i == N_NODES - 1) {
        for (int g = bc + 1; g <= N_GRAPHS; g++) g_goff[g] = N_NODES;
    }
}

// ---------------- CSR neighbor-sum aggregation ------------------------------
template <int C4>
__global__ void agg_csr_kernel(const float* __restrict__ in, int in_stride) {
    int idx = blockIdx.x * blockDim.x + threadIdx.x;
    if (idx >= N_NODES * C4) return;
    int node = idx / C4;
    int c = (idx % C4) * 4;
    int e0 = g_eoff[node], e1 = g_eoff[node + 1];
    float4 acc = make_float4(0.f, 0.f, 0.f, 0.f);
    for (int e = e0; e < e1; e++) {
        int s = g_esrc[e];
        float4 v = *(const float4*)(in + (size_t)s * in_stride + c);
        acc.x += v.x; acc.y += v.y; acc.z += v.z; acc.w += v.w;
    }
    *(float4*)(g_msg + (size_t)node * (C4 * 4) + c) = acc;
}

// ---------------- fp16 3-term emulation helpers ------------------------------
__device__ __forceinline__ void split_pack(float v0, float v1, uint32_t& hi, uint32_t& lo) {
    __half h0 = __float2half_rn(v0);
    __half h1 = __float2half_rn(v1);
    __half l0 = __float2half_rn(v0 - __half2float(h0));
    __half l1 = __float2half_rn(v1 - __half2float(h1));
    __half2 H = __halves2half2(h0, h1);
    __half2 L = __halves2half2(l0, l1);
    hi = *(uint32_t*)&H;
    lo = *(uint32_t*)&L;
}

__device__ __forceinline__ void mma_f16(float* c, const uint32_t* a, const uint32_t* b) {
    asm volatile(
        "mma.sync.aligned.m16n8k16.row.col.f32.f16.f16.f32 "
        "{%0,%1,%2,%3}, {%4,%5,%6,%7}, {%8,%9}, {%0,%1,%2,%3};"
        : "+f"(c[0]), "+f"(c[1]), "+f"(c[2]), "+f"(c[3])
        : "r"(a[0]), "r"(a[1]), "r"(a[2]), "r"(a[3]), "r"(b[0]), "r"(b[1]));
}

__device__ __forceinline__ void red_add(float* p, float v) {
    asm volatile("red.global.add.f32 [%0], %1;" :: "l"(p), "f"(v) : "memory");
}

// ---------------- bucketed grouped GEMM (3xFP16) + fused logit partials -----
// A = [msg | x], K = 2*CIN, rows via g_perm (each 128-row tile = one bucket)
// B = [Wl[d] ; Wr[d]]; out = A@B + bl[d]; also logit[n] += h_row . Wf[cat_off+...]
template <int CIN, int COUT>
__launch_bounds__(256, 2)
__global__ void gemm_kernel(const float* __restrict__ in, int in_stride,
                            float* __restrict__ out, int out_stride,
                            const float* __restrict__ Wl,
                            const float* __restrict__ bl,
                            const float* __restrict__ Wr,
                            const float* __restrict__ Wf, int cat_off) {
    constexpr int K = 2 * CIN;
    constexpr int NCH = K / 16;
    __shared__ uint32_t AsH[8][136];   // [k2][row], 136 -> bank rotate 8 per k2
    __shared__ uint32_t AsL[8][136];
    __shared__ uint32_t BsH[8][136];   // [k2][col]
    __shared__ uint32_t BsL[8][136];

    const int row0 = blockIdx.x * 128;
    if (row0 >= g_pad_off[6]) return;

    int d = 0;
    #pragma unroll
    for (int b = 1; b < 6; b++)
        if (row0 >= g_pad_off[b]) d = b;

    const int ocol0 = blockIdx.y * 128;
    const int t = threadIdx.x;
    const int lane = t & 31;
    const int warp = t >> 5;
    const int wm = (warp >> 2) * 64;      // warp row base
    const int wn = (warp & 3) * 32;       // warp col base
    const int lq = lane & 3;              // quad index (k2 offset)
    const int lg = lane >> 2;             // group index

    // A loader: 2 threads per row, 8 consecutive k (= 4 k-pairs) each
    const int arow = t >> 1, akb = (t & 1) * 8, ak2 = (t & 1) * 4;
    const int anode = g_perm[row0 + arow];
    // B loader: t>>5 = k2 (0..7), (t&31)*4 = col block of 4
    const int bk2 = t >> 5, bcb = (t & 31) * 4;

    const float* WlB = Wl + (size_t)d * CIN * COUT;
    const float* WrB = Wr + (size_t)d * CIN * COUT;

    float acc[4][4][4];
    #pragma unroll
    for (int mt = 0; mt < 4; mt++)
        #pragma unroll
        for (int nt = 0; nt < 4; nt++)
            #pragma unroll
            for (int i = 0; i < 4; i++) acc[mt][nt][i] = 0.f;

    float ar[8], br0[4], br1[4];

    auto load_regs = [&](int k0) {
        int ka = k0 + akb;
        if (anode >= 0) {
            const float* s = (ka < CIN) ? (g_msg + (size_t)anode * CIN + ka)
                                        : (in + (size_t)anode * in_stride + (ka - CIN));
            *(float4*)&ar[0] = *(const float4*)s;
            *(float4*)&ar[4] = *(const float4*)(s + 4);
        } else {
            #pragma unroll
            for (int i = 0; i < 8; i++) ar[i] = 0.f;
        }
        int kb0 = k0 + 2 * bk2;
        const float* w0 = (kb0 < CIN) ? (WlB + (size_t)kb0 * COUT + ocol0 + bcb)
                                      : (WrB + (size_t)(kb0 - CIN) * COUT + ocol0 + bcb);
        int kb1 = kb0 + 1;
        const float* w1 = (kb1 < CIN) ? (WlB + (size_t)kb1 * COUT + ocol0 + bcb)
                                      : (WrB + (size_t)(kb1 - CIN) * COUT + ocol0 + bcb);
        *(float4*)&br0[0] = *(const float4*)w0;
        *(float4*)&br1[0] = *(const float4*)w1;
    };

    auto store_smem = [&]() {
        #pragma unroll
        for (int j = 0; j < 4; j++) {
            uint32_t h, l;
            split_pack(ar[2 * j], ar[2 * j + 1], h, l);
            AsH[ak2 + j][arow] = h;
            AsL[ak2 + j][arow] = l;
        }
        uint4 h4, l4;
        split_pack(br0[0], br1[0], h4.x, l4.x);
        split_pack(br0[1], br1[1], h4.y, l4.y);
        split_pack(br0[2], br1[2], h4.z, l4.z);
        split_pack(br0[3], br1[3], h4.w, l4.w);
        *(uint4*)&BsH[bk2][bcb] = h4;
        *(uint4*)&BsL[bk2][bcb] = l4;
    };

    load_regs(0);

    for (int ch = 0; ch < NCH; ch++) {
        __syncthreads();          // previous chunk's compute done
        store_smem();
        __syncthreads();
        if (ch + 1 < NCH) load_regs((ch + 1) * 16);   // prefetch overlaps compute

        uint32_t bh[4][2], blo[4][2];
        #pragma unroll
        for (int nt = 0; nt < 4; nt++) {
            int cb = wn + nt * 8 + lg;
            bh[nt][0]  = BsH[lq][cb];
            bh[nt][1]  = BsH[lq + 4][cb];
            blo[nt][0] = BsL[lq][cb];
            blo[nt][1] = BsL[lq + 4][cb];
        }
        #pragma unroll
        for (int mt = 0; mt < 4; mt++) {
            int rb = wm + mt * 16 + lg;
            uint32_t ah[4], al[4];
            ah[0] = AsH[lq][rb];     ah[1] = AsH[lq][rb + 8];
            ah[2] = AsH[lq + 4][rb]; ah[3] = AsH[lq + 4][rb + 8];
            al[0] = AsL[lq][rb];     al[1] = AsL[lq][rb + 8];
            al[2] = AsL[lq + 4][rb]; al[3] = AsL[lq + 4][rb + 8];
            #pragma unroll
            for (int nt = 0; nt < 4; nt++) {
                mma_f16(acc[mt][nt], ah, blo[nt]);   // hi * lo
                mma_f16(acc[mt][nt], al, bh[nt]);    // lo * hi
                mma_f16(acc[mt][nt], ah, bh[nt]);    // hi * hi
            }
        }
    }

    // ---- epilogue: +bias, write h, accumulate logit partials ----------------
    // s[mt][0..3] = (row0,out0),(row0,out1),(row1,out0),(row1,out1)
    float s[4][4];
    #pragma unroll
    for (int mt = 0; mt < 4; mt++)
        #pragma unroll
        for (int i = 0; i < 4; i++) s[mt][i] = 0.f;

    #pragma unroll
    for (int mt = 0; mt < 4; mt++) {
        int r0 = row0 + wm + mt * 16 + lg;
        int n0 = g_perm[r0];
        int n1 = g_perm[r0 + 8];
        #pragma unroll
        for (int nt = 0; nt < 4; nt++) {
            int col = wn + nt * 8 + 2 * lq;
            float b0 = bl[(size_t)d * COUT + ocol0 + col];
            float b1 = bl[(size_t)d * COUT + ocol0 + col + 1];
            int gcol = cat_off + ocol0 + col;
            float wf00 = Wf[(size_t)gcol * 2 + 0], wf01 = Wf[(size_t)gcol * 2 + 1];
            float wf10 = Wf[(size_t)(gcol + 1) * 2 + 0], wf11 = Wf[(size_t)(gcol + 1) * 2 + 1];

            float v0 = acc[mt][nt][0] + b0, v1 = acc[mt][nt][1] + b1;
            float v2 = acc[mt][nt][2] + b0, v3 = acc[mt][nt][3] + b1;

            if (n0 >= 0) *(float2*)(out + (size_t)n0 * out_stride + ocol0 + col) = make_float2(v0, v1);
            if (n1 >= 0) *(float2*)(out + (size_t)n1 * out_stride + ocol0 + col) = make_float2(v2, v3);

            s[mt][0] += v0 * wf00 + v1 * wf10;
            s[mt][1] += v0 * wf01 + v1 * wf11;
            s[mt][2] += v2 * wf00 + v3 * wf10;
            s[mt][3] += v2 * wf01 + v3 * wf11;
        }
    }
    // reduce over the 4 lanes (lq) sharing the same rows, then one red per row/out
    #pragma unroll
    for (int mt = 0; mt < 4; mt++) {
        #pragma unroll
        for (int i = 0; i < 4; i++) {
            s[mt][i] += __shfl_xor_sync(0xFFFFFFFFu, s[mt][i], 1);
            s[mt][i] += __shfl_xor_sync(0xFFFFFFFFu, s[mt][i], 2);
        }
        if (lq == 0) {
            int r0 = row0 + wm + mt * 16 + lg;
            int n0 = g_perm[r0];
            int n1 = g_perm[r0 + 8];
            if (n0 >= 0) {
                red_add(&g_logit[(size_t)n0 * 2 + 0], s[mt][0]);
                red_add(&g_logit[(size_t)n0 * 2 + 1], s[mt][1]);
            }
            if (n1 >= 0) {
                red_add(&g_logit[(size_t)n1 * 2 + 0], s[mt][2]);
                red_add(&g_logit[(size_t)n1 * 2 + 1], s[mt][3]);
            }
        }
    }
}

// ---------------- segmented global add pool of h3 over batch -----------------
__global__ void pool_seg_kernel() {
    int idx = blockIdx.x * blockDim.x + threadIdx.x;
    if (idx >= N_GRAPHS * 64) return;
    int g = idx >> 6;
    int c = (idx & 63) * 4;
    int i0 = g_goff[g], i1 = g_goff[g + 1];
    float4 acc = make_float4(0.f, 0.f, 0.f, 0.f);
    for (int i = i0; i < i1; i++) {
        float4 v = *(const float4*)(g_h3 + (size_t)i * 256 + c);
        acc.x += v.x; acc.y += v.y; acc.z += v.z; acc.w += v.w;
    }
    *(float4*)(g_pool + (size_t)g * 256 + c) = acc;
}

// ---------------- per-graph pooled logits: pgl[g] = pool[g] . Wf[768..1024] --
__global__ void pgl_kernel(const float* __restrict__ Wf) {
    int g = blockIdx.x * blockDim.x + threadIdx.x;
    if (g >= N_GRAPHS) return;
    float a0 = 0.f, a1 = 0.f;
    const float* p = g_pool + (size_t)g * 256;
    for (int c = 0; c < 256; c++) {
        float v = p[c];
        a0 += v * Wf[(size_t)(768 + c) * 2 + 0];
        a1 += v * Wf[(size_t)(768 + c) * 2 + 1];
    }
    g_pgl[(size_t)g * 2 + 0] = a0;
    g_pgl[(size_t)g * 2 + 1] = a1;
}

// ---------------- final: softmax(logit + pgl[batch] + bf) --------------------
__global__ void out_kernel(const int* __restrict__ batch, const float* __restrict__ bf,
                           float* __restrict__ out) {
    int n = blockIdx.x * blockDim.x + threadIdx.x;
    if (n >= N_NODES) return;
    int g = batch[n];
    float l0 = g_logit[(size_t)n * 2 + 0] + g_pgl[(size_t)g * 2 + 0] + bf[0];
    float l1 = g_logit[(size_t)n * 2 + 1] + g_pgl[(size_t)g * 2 + 1] + bf[1];
    float m = fmaxf(l0, l1);
    float e0 = expf(l0 - m), e1 = expf(l1 - m);
    float inv = 1.f / (e0 + e1);
    out[(size_t)n * 2 + 0] = e0 * inv;
    out[(size_t)n * 2 + 1] = e1 * inv;
}

// ---------------- host orchestration ----------------------------------------
extern "C" void kernel_launch(void* const* d_in, const int* in_sizes, int n_in,
                              void* d_out, int out_size) {
    const float* x     = (const float*)d_in[0];
    const int*   ei    = (const int*)d_in[1];
    const int*   batch = (const int*)d_in[2];
    const float* Wl[4] = {(const float*)d_in[3], (const float*)d_in[6], (const float*)d_in[9],  (const float*)d_in[12]};
    const float* bl[4] = {(const float*)d_in[4], (const float*)d_in[7], (const float*)d_in[10], (const float*)d_in[13]};
    const float* Wr[4] = {(const float*)d_in[5], (const float*)d_in[8], (const float*)d_in[11], (const float*)d_in[14]};
    const float* Wf = (const float*)d_in[15];
    const float* bf = (const float*)d_in[16];
    float* out = (float*)d_out;

    const int* src = ei;
    const int* dst = ei + N_EDGES;

    void *p_deg, *p_cnt, *p_cur, *p_perm, *p_ecur, *p_h0, *p_h1, *p_h2, *p_h3, *p_logit;
    cudaGetSymbolAddress(&p_deg, g_deg);
    cudaGetSymbolAddress(&p_cnt, g_cnt);
    cudaGetSymbolAddress(&p_cur, g_cur);
    cudaGetSymbolAddress(&p_perm, g_perm);
    cudaGetSymbolAddress(&p_ecur, g_ecur);
    cudaGetSymbolAddress(&p_h0, g_h0);
    cudaGetSymbolAddress(&p_h1, g_h1);
    cudaGetSymbolAddress(&p_h2, g_h2);
    cudaGetSymbolAddress(&p_h3, g_h3);
    cudaGetSymbolAddress(&p_logit, g_logit);

    // ---- degree + bucketed permutation + CSR + graph offsets
    cudaMemsetAsync(p_deg, 0, N_NODES * sizeof(int));
    cudaMemsetAsync(p_cnt, 0, 8 * sizeof(int));
    cudaMemsetAsync(p_cur, 0, 8 * sizeof(int));
    cudaMemsetAsync(p_ecur, 0, N_NODES * sizeof(int));
    cudaMemsetAsync(p_perm, 0xFF, PERM_SZ * sizeof(int));   // -1 everywhere
    cudaMemsetAsync(p_logit, 0, (size_t)N_NODES * 2 * sizeof(float));

    deg_kernel<<<(N_EDGES + 255) / 256, 256>>>(dst);
    count_kernel<<<(N_NODES + 255) / 256, 256>>>();
    scan_kernel<<<1, 32>>>();
    scatter_kernel<<<(N_NODES + 255) / 256, 256>>>();
    scan_deg_kernel<<<1, 1024>>>();
    csr_scatter_kernel<<<(N_EDGES + 255) / 256, 256>>>(src, dst);
    goff_kernel<<<(N_NODES + 255) / 256, 256>>>(batch);

    // ---- layer 0: c_in=64 (x, stride 64) -> h0 (stride 128), cat cols [0,128)
    agg_csr_kernel<16><<<(N_NODES * 16 + 255) / 256, 256>>>(x, IN_FEAT);
    gemm_kernel<64, 128><<<dim3(N_TILES, 1), 256>>>(x, IN_FEAT, (float*)p_h0, 128,
                                                    Wl[0], bl[0], Wr[0], Wf, 0);

    // ---- layer 1: h0 -> h1 (stride 128), cat cols [128,256)
    agg_csr_kernel<32><<<(N_NODES * 32 + 255) / 256, 256>>>((const float*)p_h0, 128);
    gemm_kernel<128, 128><<<dim3(N_TILES, 1), 256>>>((const float*)p_h0, 128, (float*)p_h1, 128,
                                                     Wl[1], bl[1], Wr[1], Wf, 128);

    // ---- layer 2: h1 -> h2 (stride 256), cat cols [256,512)
    agg_csr_kernel<32><<<(N_NODES * 32 + 255) / 256, 256>>>((const float*)p_h1, 128);
    gemm_kernel<128, 256><<<dim3(N_TILES, 2), 256>>>((const float*)p_h1, 128, (float*)p_h2, 256,
                                                     Wl[2], bl[2], Wr[2], Wf, 256);

    // ---- layer 3: h2 -> h3 (stride 256), cat cols [512,768)
    agg_csr_kernel<64><<<(N_NODES * 64 + 255) / 256, 256>>>((const float*)p_h2, 256);
    gemm_kernel<256, 256><<<dim3(N_TILES, 2), 256>>>((const float*)p_h2, 256, (float*)p_h3, 256,
                                                     Wl[3], bl[3], Wr[3], Wf, 512);

    // ---- pool of h3, pooled logits, final softmax
    pool_seg_kernel<<<(N_GRAPHS * 64 + 255) / 256, 256>>>();
    pgl_kernel<<<(N_GRAPHS + 255) / 256, 256>>>(Wf);
    out_kernel<<<(N_NODES + 255) / 256, 256>>>(batch, bf, out);
}